// round 3
// baseline (speedup 1.0000x reference)
#include <cuda_runtime.h>

#define Hd 768
#define BGRAPH 256
#define AOUT 3129

// Scratch (no allocations allowed): lang_g [256, 2304], mid1/mid2 [256, 768]
__device__ float g_langg[BGRAPH * 3 * Hd];
__device__ float g_mid1[BGRAPH * Hd];
__device__ float g_mid2[BGRAPH * Hd];

// Device-side scratch selector: 0 = use external pointer, 1/2/3 = globals.
__device__ __forceinline__ float* sel_buf(int sel, float* ext) {
    switch (sel) {
        case 1: return g_langg;
        case 2: return g_mid1;
        case 3: return g_mid2;
        default: return ext;
    }
}
__device__ __forceinline__ const float* sel_buf_c(int sel, const float* ext) {
    switch (sel) {
        case 1: return g_langg;
        case 2: return g_mid2;   // only mid2 is ever a const-A global besides langg
        case 3: return g_mid1;
        default: return ext;
    }
}

__device__ __forceinline__ int lower_bound_dev(const int* __restrict__ a, int n, int v) {
    int lo = 0, hi = n;
    while (lo < hi) {
        int m = (lo + hi) >> 1;
        if (a[m] < v) lo = m + 1; else hi = m;
    }
    return lo;
}

// Segment-sum pooling. seg is sorted ascending. grid = (BGRAPH, 6), block = 128.
// Block (b, yc) sums rows of segment b over columns [yc*128, yc*128+128).
// Output goes into g_langg[b][col_base + col].
__global__ void pool_kernel(const float* __restrict__ feat, const int* __restrict__ seg,
                            int nrows, int col_base) {
    const int b   = blockIdx.x;
    const int col = blockIdx.y * 128 + threadIdx.x;
    const int start = lower_bound_dev(seg, nrows, b);
    const int end   = lower_bound_dev(seg, nrows, b + 1);
    const float* p = feat + col;
    float s0 = 0.f, s1 = 0.f, s2 = 0.f, s3 = 0.f;
    int r = start;
    for (; r + 4 <= end; r += 4) {
        s0 += p[(r + 0) * Hd];
        s1 += p[(r + 1) * Hd];
        s2 += p[(r + 2) * Hd];
        s3 += p[(r + 3) * Hd];
    }
    for (; r < end; ++r) s0 += p[r * Hd];
    g_langg[b * (3 * Hd) + col_base + col] = (s0 + s1) + (s2 + s3);
}

// C[m, 0..N) = bias[n], C selected by c_sel.  grid = (ceil(N/256), M)
__global__ void init_bias_kernel(int c_sel, int c_off, int ldc,
                                 const float* __restrict__ bias, int N) {
    float* C = sel_buf(c_sel, nullptr) + c_off;
    int n = blockIdx.x * 256 + threadIdx.x;
    if (n < N) C[blockIdx.y * ldc + n] = bias[n];
}

// Tiled fp32 GEMM: C[M,N] (+)= op(A[M,K]) @ W[K,N] (+ bias).
// BM=BN=64, BK=16, 256 threads, 4x4 thread tile.
// gridDim.z = k_splits (K % (16*z) == 0 required). ATOMIC: atomicAdd into
// bias-preinitialized C. !ATOMIC: direct store of acc + bias[n].
// a_sel/c_sel pick device scratch buffers (0 = use the passed pointer).
template <bool RELU_A, bool ATOMIC>
__global__ __launch_bounds__(256)
void gemm_kernel(int a_sel, const float* __restrict__ A_ext, int lda,
                 const float* __restrict__ W,
                 const float* __restrict__ bias,
                 int c_sel, float* __restrict__ C_ext, int c_off, int ldc,
                 int M, int N, int K) {
    const float* A = sel_buf_c(a_sel, A_ext);
    float* C = sel_buf(c_sel, C_ext) + c_off;

    const int BM = 64, BN = 64, BK = 16;
    __shared__ float As[BK][BM + 4];   // +4 pad: keeps 16B alignment, kills STS conflicts
    __shared__ float Ws[BK][BN];

    const int tid = threadIdx.x;
    const int tx = tid & 15;          // 16 col-groups
    const int ty = tid >> 4;          // 16 row-groups
    const int bm = blockIdx.x * BM;
    const int bn = blockIdx.y * BN;
    const int Kc = K / gridDim.z;
    const int k0 = blockIdx.z * Kc;

    float acc[4][4] = {};

    for (int ks = k0; ks < k0 + Kc; ks += BK) {
        // Load A tile: 64 rows x 16 cols = 1024 elems, 4 per thread
        #pragma unroll
        for (int i = 0; i < 4; i++) {
            int e = tid + i * 256;
            int r = e >> 4, c = e & 15;
            float v = A[(bm + r) * lda + ks + c];
            if (RELU_A) v = fmaxf(v, 0.f);
            As[c][r] = v;
        }
        // Load W tile: 16 rows x 64 cols, 4 per thread (guard N edge)
        #pragma unroll
        for (int i = 0; i < 4; i++) {
            int e = tid + i * 256;
            int r = e >> 6, c = e & 63;
            int n = bn + c;
            Ws[r][c] = (n < N) ? W[(ks + r) * N + n] : 0.f;
        }
        __syncthreads();

        #pragma unroll
        for (int k = 0; k < BK; k++) {
            float a[4], b[4];
            #pragma unroll
            for (int i = 0; i < 4; i++) a[i] = As[k][ty * 4 + i];
            #pragma unroll
            for (int j = 0; j < 4; j++) b[j] = Ws[k][tx * 4 + j];
            #pragma unroll
            for (int i = 0; i < 4; i++)
                #pragma unroll
                for (int j = 0; j < 4; j++)
                    acc[i][j] += a[i] * b[j];
        }
        __syncthreads();
    }

    #pragma unroll
    for (int i = 0; i < 4; i++) {
        int m = bm + ty * 4 + i;
        #pragma unroll
        for (int j = 0; j < 4; j++) {
            int n = bn + tx * 4 + j;
            if (n < N) {
                if (ATOMIC) atomicAdd(&C[m * ldc + n], acc[i][j]);
                else        C[m * ldc + n] = acc[i][j] + bias[n];
            }
        }
    }
}

extern "C" void kernel_launch(void* const* d_in, const int* in_sizes, int n_in,
                              void* d_out, int out_size) {
    const float* node_feat = (const float*)d_in[0];
    const float* edge_feat = (const float*)d_in[1];
    const float* question  = (const float*)d_in[2];
    const int*   node_seg  = (const int*)  d_in[3];
    const int*   edge_seg  = (const int*)  d_in[4];
    const float* W_lang    = (const float*)d_in[5];
    const float* b_lang    = (const float*)d_in[6];
    const float* W_mid     = (const float*)d_in[7];
    const float* b_mid     = (const float*)d_in[8];
    const float* W_mid2    = (const float*)d_in[9];
    const float* b_mid2    = (const float*)d_in[10];
    const float* W_ans     = (const float*)d_in[11];
    const float* b_ans     = (const float*)d_in[12];
    float* pred = (float*)d_out;

    const int Nn = in_sizes[3];   // node count
    const int Ne = in_sizes[4];   // edge count

    // 1-2: segment-sum pooling -> lang_g[:, 0:768] and [:, 768:1536]
    pool_kernel<<<dim3(BGRAPH, 6), 128>>>(node_feat, node_seg, Nn, 0);
    pool_kernel<<<dim3(BGRAPH, 6), 128>>>(edge_feat, edge_seg, Ne, Hd);

    // 3-4: lang = q @ W_lang + b_lang -> lang_g[:, 1536:2304]  (split-K=3, atomic)
    init_bias_kernel<<<dim3(3, BGRAPH), 256>>>(1, 2 * Hd, 3 * Hd, b_lang, Hd);
    gemm_kernel<false, true><<<dim3(4, 12, 3), 256>>>(
        0, question, Hd, W_lang, nullptr, 1, nullptr, 2 * Hd, 3 * Hd, BGRAPH, Hd, Hd);

    // 5-6: mid1 = lang_g @ W_mid + b_mid   (relu deferred, split-K=3)
    init_bias_kernel<<<dim3(3, BGRAPH), 256>>>(2, 0, Hd, b_mid, Hd);
    gemm_kernel<false, true><<<dim3(4, 12, 3), 256>>>(
        1, nullptr, 3 * Hd, W_mid, nullptr, 2, nullptr, 0, Hd, BGRAPH, Hd, 3 * Hd);

    // 7-8: mid2 = relu(mid1) @ W_mid2 + b_mid2  (relu deferred, split-K=3)
    init_bias_kernel<<<dim3(3, BGRAPH), 256>>>(3, 0, Hd, b_mid2, Hd);
    gemm_kernel<true, true><<<dim3(4, 12, 3), 256>>>(
        3, nullptr, Hd, W_mid2, nullptr, 3, nullptr, 0, Hd, BGRAPH, Hd, Hd);

    // 9: pred = relu(mid2) @ W_ans + b_ans  (196 blocks, direct store)
    gemm_kernel<true, false><<<dim3(4, (AOUT + 63) / 64, 1), 256>>>(
        2, nullptr, Hd, W_ans, b_ans, 0, pred, 0, AOUT, BGRAPH, AOUT, Hd);
}

// round 4
// speedup vs baseline: 1.2129x; 1.2129x over previous
#include <cuda_runtime.h>

#define Hd 768
#define HV4 192          // Hd / 4 (float4 per row)
#define BGRAPH 256
#define AOUT 3129
#define SSPLIT 6         // row-splits per segment in pooling

// ---- device scratch (no allocations allowed) ----
__device__ int   g_bounds[2][BGRAPH + 1];                       // node / edge segment bounds
__device__ float g_partial[2][SSPLIT][BGRAPH][Hd];              // pooling partials (9.4 MB)
__device__ float g_langg[BGRAPH * 3 * Hd];                      // [256, 2304]
__device__ float g_mid1[BGRAPH * Hd];
__device__ float g_mid2[BGRAPH * Hd];

// Scratch selector: 0 = external pointer, 1 = langg, 2 = mid1, 3 = mid2.
__device__ __forceinline__ float* sel_buf(int sel, float* ext) {
    switch (sel) { case 1: return g_langg; case 2: return g_mid1; case 3: return g_mid2;
                   default: return ext; }
}
__device__ __forceinline__ const float* sel_buf_c(int sel, const float* ext) {
    switch (sel) { case 1: return g_langg; case 2: return g_mid1; case 3: return g_mid2;
                   default: return ext; }
}

__device__ __forceinline__ float4 f4add(float4 a, float4 b) {
    a.x += b.x; a.y += b.y; a.z += b.z; a.w += b.w; return a;
}

// ---- 1. segment bounds, once. grid=2 (node, edge), block=257 ----
__global__ void bounds_kernel(const int* __restrict__ node_seg, int nn,
                              const int* __restrict__ edge_seg, int ne) {
    const int* seg = blockIdx.x ? edge_seg : node_seg;
    const int  n   = blockIdx.x ? ne : nn;
    const int  v   = threadIdx.x;                // 0..256
    int lo = 0, hi = n;
    while (lo < hi) { int m = (lo + hi) >> 1; if (seg[m] < v) lo = m + 1; else hi = m; }
    g_bounds[blockIdx.x][v] = lo;
}

// ---- 2. pooling partial sums. grid=(BGRAPH, SSPLIT, 2), block=192 ----
// Block (b, s, z): sums a contiguous 1/S row-chunk of segment b of tensor z,
// full row width via float4 (LDG.128, 4-row unroll => MLP 4).
__global__ __launch_bounds__(HV4)
void pool_partial_kernel(const float* __restrict__ node_feat,
                         const float* __restrict__ edge_feat) {
    const int b = blockIdx.x, s = blockIdx.y, z = blockIdx.z;
    const float4* feat = (const float4*)(z ? edge_feat : node_feat);
    const int start = g_bounds[z][b];
    const int end   = g_bounds[z][b + 1];
    const int len   = end - start;
    const int chunk = (len + SSPLIT - 1) / SSPLIT;
    const int r0 = start + s * chunk;
    const int r1 = min(r0 + chunk, end);
    const int c = threadIdx.x;                   // float4 column 0..191

    float4 a0 = {0,0,0,0}, a1 = {0,0,0,0}, a2 = {0,0,0,0}, a3 = {0,0,0,0};
    const float4* p = feat + c;
    int r = r0;
    for (; r + 4 <= r1; r += 4) {
        a0 = f4add(a0, p[(size_t)(r + 0) * HV4]);
        a1 = f4add(a1, p[(size_t)(r + 1) * HV4]);
        a2 = f4add(a2, p[(size_t)(r + 2) * HV4]);
        a3 = f4add(a3, p[(size_t)(r + 3) * HV4]);
    }
    for (; r < r1; ++r) a0 = f4add(a0, p[(size_t)r * HV4]);
    float4 t = f4add(f4add(a0, a1), f4add(a2, a3));
    ((float4*)&g_partial[z][s][b][0])[c] = t;
}

// ---- 3. reduce partials -> lang_g columns. grid=(BGRAPH, 2), block=192 ----
__global__ void pool_reduce_kernel() {
    const int b = blockIdx.x, z = blockIdx.y, c = threadIdx.x;
    float4 acc = {0,0,0,0};
    #pragma unroll
    for (int s = 0; s < SSPLIT; s++)
        acc = f4add(acc, ((const float4*)&g_partial[z][s][b][0])[c]);
    ((float4*)&g_langg[b * (3 * Hd) + z * Hd])[c] = acc;
}

// ---- bias pre-init for split-K atomic GEMMs. grid=(ceil(N/256), M) ----
__global__ void init_bias_kernel(int c_sel, float* C_ext, int c_off, int ldc,
                                 const float* __restrict__ bias, int N) {
    float* C = sel_buf(c_sel, C_ext) + c_off;
    int n = blockIdx.x * 256 + threadIdx.x;
    if (n < N) C[blockIdx.y * ldc + n] = bias[n];
}

// ---- tiled fp32 GEMM: C[M,N] (+)= op(A) @ W (+ bias) ----
// BM=BN=64, BK=16, 256 threads, 4x4 tile, float4 LDS in inner loop.
// gridDim.z = k_splits; ATOMIC => atomicAdd into bias-preinit C.
template <bool RELU_A, bool ATOMIC>
__global__ __launch_bounds__(256)
void gemm_kernel(int a_sel, const float* __restrict__ A_ext, int lda,
                 const float* __restrict__ W,
                 const float* __restrict__ bias,
                 int c_sel, float* __restrict__ C_ext, int c_off, int ldc,
                 int M, int N, int K) {
    const float* A = sel_buf_c(a_sel, A_ext);
    float* C = sel_buf(c_sel, C_ext) + c_off;

    const int BM = 64, BN = 64, BK = 16;
    __shared__ float As[BK][BM + 4];   // row = 272 B (16B-aligned)
    __shared__ float Ws[BK][BN];

    const int tid = threadIdx.x;
    const int tx = tid & 15;
    const int ty = tid >> 4;
    const int bm = blockIdx.x * BM;
    const int bn = blockIdx.y * BN;
    const int Kc = K / gridDim.z;
    const int k0 = blockIdx.z * Kc;

    float acc[4][4] = {};

    for (int ks = k0; ks < k0 + Kc; ks += BK) {
        #pragma unroll
        for (int i = 0; i < 4; i++) {
            int e = tid + i * 256;
            int r = e >> 4, c = e & 15;
            float v = A[(bm + r) * lda + ks + c];
            if (RELU_A) v = fmaxf(v, 0.f);
            As[c][r] = v;
        }
        #pragma unroll
        for (int i = 0; i < 4; i++) {
            int e = tid + i * 256;
            int r = e >> 6, c = e & 63;
            int n = bn + c;
            Ws[r][c] = (n < N) ? W[(ks + r) * N + n] : 0.f;
        }
        __syncthreads();

        #pragma unroll
        for (int k = 0; k < BK; k++) {
            float4 a = *reinterpret_cast<const float4*>(&As[k][ty * 4]);
            float4 b = *reinterpret_cast<const float4*>(&Ws[k][tx * 4]);
            const float av[4] = {a.x, a.y, a.z, a.w};
            const float bv[4] = {b.x, b.y, b.z, b.w};
            #pragma unroll
            for (int i = 0; i < 4; i++)
                #pragma unroll
                for (int j = 0; j < 4; j++)
                    acc[i][j] += av[i] * bv[j];
        }
        __syncthreads();
    }

    #pragma unroll
    for (int i = 0; i < 4; i++) {
        int m = bm + ty * 4 + i;
        #pragma unroll
        for (int j = 0; j < 4; j++) {
            int n = bn + tx * 4 + j;
            if (n < N) {
                if (ATOMIC) atomicAdd(&C[m * ldc + n], acc[i][j]);
                else        C[m * ldc + n] = acc[i][j] + bias[n];
            }
        }
    }
}

extern "C" void kernel_launch(void* const* d_in, const int* in_sizes, int n_in,
                              void* d_out, int out_size) {
    const float* node_feat = (const float*)d_in[0];
    const float* edge_feat = (const float*)d_in[1];
    const float* question  = (const float*)d_in[2];
    const int*   node_seg  = (const int*)  d_in[3];
    const int*   edge_seg  = (const int*)  d_in[4];
    const float* W_lang    = (const float*)d_in[5];
    const float* b_lang    = (const float*)d_in[6];
    const float* W_mid     = (const float*)d_in[7];
    const float* b_mid     = (const float*)d_in[8];
    const float* W_mid2    = (const float*)d_in[9];
    const float* b_mid2    = (const float*)d_in[10];
    const float* W_ans     = (const float*)d_in[11];
    const float* b_ans     = (const float*)d_in[12];
    float* pred = (float*)d_out;

    const int Nn = in_sizes[3];
    const int Ne = in_sizes[4];

    // 1. segment bounds (both tensors)
    bounds_kernel<<<2, BGRAPH + 1>>>(node_seg, Nn, edge_seg, Ne);

    // 2-3. pooling: partials then reduce -> lang_g[:, 0:1536]
    pool_partial_kernel<<<dim3(BGRAPH, SSPLIT, 2), HV4>>>(node_feat, edge_feat);
    pool_reduce_kernel<<<dim3(BGRAPH, 2), HV4>>>();

    // 4. lang = q @ W_lang + b_lang -> lang_g[:, 1536:2304]   (split-K=6)
    init_bias_kernel<<<dim3(3, BGRAPH), 256>>>(1, nullptr, 2 * Hd, 3 * Hd, b_lang, Hd);
    gemm_kernel<false, true><<<dim3(4, 12, 6), 256>>>(
        0, question, Hd, W_lang, nullptr, 1, nullptr, 2 * Hd, 3 * Hd, BGRAPH, Hd, Hd);

    // 5. mid1 = lang_g @ W_mid + b_mid                        (split-K=6)
    init_bias_kernel<<<dim3(3, BGRAPH), 256>>>(2, nullptr, 0, Hd, b_mid, Hd);
    gemm_kernel<false, true><<<dim3(4, 12, 6), 256>>>(
        1, nullptr, 3 * Hd, W_mid, nullptr, 2, nullptr, 0, Hd, BGRAPH, Hd, 3 * Hd);

    // 6. mid2 = relu(mid1) @ W_mid2 + b_mid2                  (split-K=6)
    init_bias_kernel<<<dim3(3, BGRAPH), 256>>>(3, nullptr, 0, Hd, b_mid2, Hd);
    gemm_kernel<true, true><<<dim3(4, 12, 6), 256>>>(
        2, nullptr, Hd, W_mid2, nullptr, 3, nullptr, 0, Hd, BGRAPH, Hd, Hd);

    // 7. pred = relu(mid2) @ W_ans + b_ans                    (split-K=2)
    init_bias_kernel<<<dim3((AOUT + 255) / 256, BGRAPH), 256>>>(
        0, pred, 0, AOUT, b_ans, AOUT);
    gemm_kernel<true, true><<<dim3(4, (AOUT + 63) / 64, 2), 256>>>(
        3, nullptr, Hd, W_ans, nullptr, 0, pred, 0, AOUT, BGRAPH, AOUT, Hd);
}